// round 11
// baseline (speedup 1.0000x reference)
#include <cuda_runtime.h>
#include <cuda_bf16.h>

// DurationCalculator:
//   weights_argmax[b,y] = duration[b,y] + (y < output_length[b] ? 0 : -10000)
//   durations[b,x]      = count over y of (weights_argmax[b,y] == x), 0 <= x < X
// Output (float32): [ weights_argmax (B*Y) | durations (B*X) ]
//
// One CTA per row, 256 threads (8 warps). ATOMIC-FREE histogram:
//   - each warp owns a private smem histogram (no inter-warp races)
//   - intra-warp duplicate bins resolved exactly with __match_any_sync:
//     group leader adds popc(group_mask) via plain LDS+IADD+STS
//   - merge: per-bin sum of the 8 warp histograms (bank-conflict-free via
//     stride padding), written as float4.
// This moves the histogram off the ~2 cyc/lane smem atomic unit onto the
// full-rate LDS/STS crossbar.

#ifndef MASK_PENALTY
#define MASK_PENALTY (-10000)
#endif

#define NWARPS   8
#define HSTRIDE  (1024 + 8)   // pad: merge reads hist[w][x] conflict-free

__global__ void __launch_bounds__(256)
duration_calc_kernel(const int* __restrict__ duration,
                     const int* __restrict__ output_length,
                     float* __restrict__ w_out,
                     float* __restrict__ h_out,
                     int Y, int X)
{
    __shared__ int hist[NWARPS][HSTRIDE];   // 33 KB

    const int b    = blockIdx.x;
    const int tid  = threadIdx.x;
    const int nt   = blockDim.x;            // 256
    const int wid  = tid >> 5;
    int* __restrict__ myhist = hist[wid];

    // Zero all warp histograms (int4 stores; NWARPS*HSTRIDE % 4 == 0)
    {
        int4* hz = reinterpret_cast<int4*>(&hist[0][0]);
        const int nz = (NWARPS * HSTRIDE) >> 2;
        int4 z = make_int4(0, 0, 0, 0);
        for (int i = tid; i < nz; i += nt) hz[i] = z;
    }
    __syncthreads();

    const int L = output_length[b];

    const int4* __restrict__ dur4 = reinterpret_cast<const int4*>(duration + (size_t)b * Y);
    float4* __restrict__ w4       = reinterpret_cast<float4*>(w_out + (size_t)b * Y);
    const int n4 = Y >> 2;                  // 1024 for Y=4096

    // Histogram one value into this warp's private histogram, exactly.
    // All lanes participate in the match (full mask); groups are homogeneous
    // in validity because masked values (< -8976) never equal valid ones.
    #define HIST_ONE(wv)                                                      \
    do {                                                                      \
        unsigned m = __match_any_sync(0xFFFFFFFFu, (wv));                     \
        int leader = __ffs(m) - 1;                                            \
        if ((int)(threadIdx.x & 31) == leader && (unsigned)(wv) < (unsigned)X)\
            myhist[(wv)] += __popc(m);                                        \
    } while (0)

    // Main loop: 4 front-batched int4 loads per thread per iteration (MLP=4).
    for (int base = tid; base < n4; base += nt * 4) {
        const int i0 = base;
        const int i1 = base + nt;
        const int i2 = base + nt * 2;
        const int i3 = base + nt * 3;
        const bool p1 = i1 < n4, p2 = i2 < n4, p3 = i3 < n4;

        int4 d0 = dur4[i0];
        int4 d1 = p1 ? dur4[i1] : make_int4(0, 0, 0, 0);
        int4 d2 = p2 ? dur4[i2] : make_int4(0, 0, 0, 0);
        int4 d3 = p3 ? dur4[i3] : make_int4(0, 0, 0, 0);

        #define PROC(dd, ii, pp)                                              \
        do {                                                                  \
            const int y = (ii) << 2;                                          \
            int wx = dd.x + ((y + 0) < L ? 0 : MASK_PENALTY);                 \
            int wy = dd.y + ((y + 1) < L ? 0 : MASK_PENALTY);                 \
            int wz = dd.z + ((y + 2) < L ? 0 : MASK_PENALTY);                 \
            int ww = dd.w + ((y + 3) < L ? 0 : MASK_PENALTY);                 \
            if (pp) {                                                         \
                float4 w;                                                     \
                w.x = (float)wx; w.y = (float)wy;                             \
                w.z = (float)wz; w.w = (float)ww;                             \
                w4[ii] = w;                                                   \
            } else { wx = wy = wz = ww = -1; }                                \
            HIST_ONE(wx);                                                     \
            HIST_ONE(wy);                                                     \
            HIST_ONE(wz);                                                     \
            HIST_ONE(ww);                                                     \
        } while (0)

        PROC(d0, i0, true);
        PROC(d1, i1, p1);
        PROC(d2, i2, p2);
        PROC(d3, i3, p3);
        #undef PROC
    }

    // Scalar tail for Y not a multiple of 4 (no-op for Y=4096).
    // Whole warps execute together (Y tail < 4*nt), so match stays collective.
    {
        const int ytail = n4 << 2;
        for (int y0 = ytail + tid; __any_sync(0xFFFFFFFFu, y0 < Y); y0 += nt) {
            int w = -1;
            if (y0 < Y) {
                w = duration[(size_t)b * Y + y0] + (y0 < L ? 0 : MASK_PENALTY);
                w_out[(size_t)b * Y + y0] = (float)w;
            }
            HIST_ONE(w);
        }
    }
    #undef HIST_ONE

    __syncthreads();

    // Merge 8 warp histograms -> global float row. Each thread sums 4
    // consecutive bins across all warps (LDS.128, conflict-free via HSTRIDE
    // padding), then stores one float4.
    float* __restrict__ hrow = h_out + (size_t)b * X;
    float4* __restrict__ hrow4 = reinterpret_cast<float4*>(hrow);
    for (int k = tid; k < (X >> 2); k += nt) {
        int sx = 0, sy = 0, sz = 0, sw = 0;
        #pragma unroll
        for (int w = 0; w < NWARPS; w++) {
            int4 v = *reinterpret_cast<const int4*>(&hist[w][k << 2]);
            sx += v.x; sy += v.y; sz += v.z; sw += v.w;
        }
        float4 o;
        o.x = (float)sx; o.y = (float)sy; o.z = (float)sz; o.w = (float)sw;
        hrow4[k] = o;
    }
    // Tail bins if X not a multiple of 4 (no-op for X=1024)
    for (int x = (X & ~3) + tid; x < X; x += nt) {
        int s = 0;
        #pragma unroll
        for (int w = 0; w < NWARPS; w++) s += hist[w][x];
        hrow[x] = (float)s;
    }
}

extern "C" void kernel_launch(void* const* d_in, const int* in_sizes, int n_in,
                              void* d_out, int out_size)
{
    const int* duration      = (const int*)d_in[0];
    const int* output_length = (const int*)d_in[1];

    const int B = in_sizes[1];          // 256
    const int Y = in_sizes[0] / B;      // 4096
    const int X = out_size / B - Y;     // 1024

    float* w_out = (float*)d_out;                   // weights_argmax: B*Y
    float* h_out = (float*)d_out + (size_t)B * Y;   // durations:      B*X

    const int threads = 256;
    duration_calc_kernel<<<B, threads>>>(duration, output_length,
                                         w_out, h_out, Y, X);
}

// round 12
// speedup vs baseline: 2.1246x; 2.1246x over previous
#include <cuda_runtime.h>
#include <cuda_bf16.h>

// DurationCalculator:
//   weights_argmax[b,y] = duration[b,y] + (y < output_length[b] ? 0 : -10000)
//   durations[b,x]      = count over y of (weights_argmax[b,y] == x), 0 <= x < X
// Output (float32): [ weights_argmax (B*Y) | durations (B*X) ]
//
// One CTA per row, 512 threads (16 warps). Dual-pipe histogram:
//   - warps 0-9  (10/16 ~ capacity-optimal 0.63): smem ATOMS into shared hist
//   - warps 10-15: REDG.ADD.F32 straight into the CTA-exclusive global row
//   (SM smem-atomic unit ~74 lanes/cyc chip and LTS atomic ALUs ~43 lanes/cyc
//    are disjoint resources; splitting ~524K increments 63/37 runs them in
//    parallel at ~2.4us instead of 3.7us on one pipe.)
// Zero global row with __stcg (L2-visible, no stale L1); after streaming,
// __threadfence + __syncthreads makes all CTA REDGs visible, then merge the
// smem partial with PLAIN __ldcg/add/__stcg (no atomics -- row is exclusive).

#ifndef MASK_PENALTY
#define MASK_PENALTY (-10000)
#endif

__global__ void __launch_bounds__(512)
duration_calc_kernel(const int* __restrict__ duration,
                     const int* __restrict__ output_length,
                     float* __restrict__ w_out,
                     float* __restrict__ h_out,
                     int Y, int X)
{
    extern __shared__ int hist[];   // X bins (4 KB for X=1024)
    const int b   = blockIdx.x;
    const int tid = threadIdx.x;
    const int nt  = blockDim.x;     // 512
    const int wid = tid >> 5;

    float* __restrict__ hrow = h_out + (size_t)b * X;

    // Zero smem hist and the exclusively-owned global row (L2-direct stores).
    for (int i = tid; i < X; i += nt) hist[i] = 0;
    {
        const float4 z = make_float4(0.f, 0.f, 0.f, 0.f);
        float4* __restrict__ hrow4 = reinterpret_cast<float4*>(hrow);
        for (int i = tid; i < (X >> 2); i += nt) __stcg(&hrow4[i], z);
    }
    __syncthreads();   // zeros happen-before any REDG/ATOMS below (cta fence)

    const int L = output_length[b];

    const int4* __restrict__ dur4 = reinterpret_cast<const int4*>(duration + (size_t)b * Y);
    float4* __restrict__ w4       = reinterpret_cast<float4*>(w_out + (size_t)b * Y);
    const int n4 = Y >> 2;          // 1024 for Y=4096

    const bool use_smem = wid < 10;   // 10/16 warps -> ATOMS, 6/16 -> REDG

    // 8 elems/thread: 2 front-batched int4 loads per iteration.
    for (int base = tid; base < n4; base += nt * 2) {
        const int i0 = base;
        const int i1 = base + nt;
        const bool p1 = i1 < n4;

        int4 d0 = dur4[i0];
        int4 d1 = p1 ? dur4[i1] : make_int4(0, 0, 0, 0);

        #define PROC(dd, ii, pp)                                               \
        do {                                                                   \
            if (pp) {                                                          \
                const int y = (ii) << 2;                                       \
                int wx = dd.x + ((y + 0) < L ? 0 : MASK_PENALTY);              \
                int wy = dd.y + ((y + 1) < L ? 0 : MASK_PENALTY);              \
                int wz = dd.z + ((y + 2) < L ? 0 : MASK_PENALTY);              \
                int ww = dd.w + ((y + 3) < L ? 0 : MASK_PENALTY);              \
                float4 w;                                                      \
                w.x = (float)wx; w.y = (float)wy;                              \
                w.z = (float)wz; w.w = (float)ww;                              \
                w4[ii] = w;                                                    \
                if (use_smem) {                                                \
                    if ((unsigned)wx < (unsigned)X) atomicAdd(&hist[wx], 1);   \
                    if ((unsigned)wy < (unsigned)X) atomicAdd(&hist[wy], 1);   \
                    if ((unsigned)wz < (unsigned)X) atomicAdd(&hist[wz], 1);   \
                    if ((unsigned)ww < (unsigned)X) atomicAdd(&hist[ww], 1);   \
                } else {                                                       \
                    if ((unsigned)wx < (unsigned)X) atomicAdd(&hrow[wx], 1.0f);\
                    if ((unsigned)wy < (unsigned)X) atomicAdd(&hrow[wy], 1.0f);\
                    if ((unsigned)wz < (unsigned)X) atomicAdd(&hrow[wz], 1.0f);\
                    if ((unsigned)ww < (unsigned)X) atomicAdd(&hrow[ww], 1.0f);\
                }                                                              \
            }                                                                  \
        } while (0)

        PROC(d0, i0, true);
        PROC(d1, i1, p1);
        #undef PROC
    }

    // Scalar tail for Y not a multiple of 4 (no-op for Y=4096)
    for (int y = (n4 << 2) + tid; y < Y; y += nt) {
        int w = duration[(size_t)b * Y + y] + (y < L ? 0 : MASK_PENALTY);
        w_out[(size_t)b * Y + y] = (float)w;
        if ((unsigned)w < (unsigned)X) atomicAdd(&hist[w], 1);
    }

    // Make this thread's REDGs visible, then rendezvous: after the barrier
    // every thread sees all CTA REDG results at L2.
    __threadfence();
    __syncthreads();

    // Atomic-free merge: row is CTA-exclusive, no other writers remain.
    // L1-bypassing loads/stores (REDG results live at L2; L1 may be stale).
    for (int i = tid; i < X; i += nt) {
        float v = __ldcg(&hrow[i]) + (float)hist[i];
        __stcg(&hrow[i], v);
    }
}

extern "C" void kernel_launch(void* const* d_in, const int* in_sizes, int n_in,
                              void* d_out, int out_size)
{
    const int* duration      = (const int*)d_in[0];
    const int* output_length = (const int*)d_in[1];

    const int B = in_sizes[1];          // 256
    const int Y = in_sizes[0] / B;      // 4096
    const int X = out_size / B - Y;     // 1024

    float* w_out = (float*)d_out;                   // weights_argmax: B*Y
    float* h_out = (float*)d_out + (size_t)B * Y;   // durations:      B*X

    const int threads = 512;
    const size_t smem = (size_t)X * sizeof(int);
    duration_calc_kernel<<<B, threads, smem>>>(duration, output_length,
                                               w_out, h_out, Y, X);
}

// round 13
// speedup vs baseline: 2.9556x; 1.3911x over previous
#include <cuda_runtime.h>
#include <cuda_bf16.h>

// DurationCalculator:
//   weights_argmax[b,y] = duration[b,y] + (y < output_length[b] ? 0 : -10000)
//   durations[b,x]      = count over y of (weights_argmax[b,y] == x), 0 <= x < X
// Output (float32): [ weights_argmax (B*Y) | durations (B*X) ]
//
// One CTA per row, 512 threads, smem histogram (ATOMS only), no global
// atomics, no merge. Issue-slot optimization: the valid/masked boundary L
// splits the row coarsely per int4 --
//   y+4 <= L : w = d        (no mask math; histogram with range-check ATOMS)
//   y   >= L : w = d-10000  (masked: NO ISETP, NO ATOMS issued at all)
//   boundary : per-element fallback (<= 1 int4 per thread-stride pass)
// This removes ~2 instructions/elem vs the select-everywhere version and all
// atomic-path issue slots from the masked half of each row.

#ifndef MASK_PENALTY
#define MASK_PENALTY (-10000)
#endif

__global__ void __launch_bounds__(512)
duration_calc_kernel(const int* __restrict__ duration,
                     const int* __restrict__ output_length,
                     float* __restrict__ w_out,
                     float* __restrict__ h_out,
                     int Y, int X)
{
    extern __shared__ int hist[];   // X bins (4 KB for X=1024)
    const int b   = blockIdx.x;
    const int tid = threadIdx.x;
    const int nt  = blockDim.x;     // 512

    for (int i = tid; i < X; i += nt) hist[i] = 0;
    __syncthreads();

    const int L = output_length[b];

    const int4* __restrict__ dur4 = reinterpret_cast<const int4*>(duration + (size_t)b * Y);
    float4* __restrict__ w4       = reinterpret_cast<float4*>(w_out + (size_t)b * Y);
    const int n4 = Y >> 2;          // 1024 for Y=4096

    for (int i = tid; i < n4; i += nt) {
        const int y = i << 2;
        int4 d = dur4[i];
        if (y + 4 <= L) {
            // fully valid: w = d, d in [0, X) by construction (guard kept cheap)
            float4 w;
            w.x = (float)d.x; w.y = (float)d.y;
            w.z = (float)d.z; w.w = (float)d.w;
            w4[i] = w;
            if ((unsigned)d.x < (unsigned)X) atomicAdd(&hist[d.x], 1);
            if ((unsigned)d.y < (unsigned)X) atomicAdd(&hist[d.y], 1);
            if ((unsigned)d.z < (unsigned)X) atomicAdd(&hist[d.z], 1);
            if ((unsigned)d.w < (unsigned)X) atomicAdd(&hist[d.w], 1);
        } else if (y >= L) {
            // fully masked: no range checks, no atomics
            float4 w;
            w.x = (float)(d.x + MASK_PENALTY);
            w.y = (float)(d.y + MASK_PENALTY);
            w.z = (float)(d.z + MASK_PENALTY);
            w.w = (float)(d.w + MASK_PENALTY);
            w4[i] = w;
        } else {
            // boundary int4 (at most one per pass)
            int wx = d.x + ((y + 0) < L ? 0 : MASK_PENALTY);
            int wy = d.y + ((y + 1) < L ? 0 : MASK_PENALTY);
            int wz = d.z + ((y + 2) < L ? 0 : MASK_PENALTY);
            int ww = d.w + ((y + 3) < L ? 0 : MASK_PENALTY);
            float4 w;
            w.x = (float)wx; w.y = (float)wy; w.z = (float)wz; w.w = (float)ww;
            w4[i] = w;
            if ((unsigned)wx < (unsigned)X) atomicAdd(&hist[wx], 1);
            if ((unsigned)wy < (unsigned)X) atomicAdd(&hist[wy], 1);
            if ((unsigned)wz < (unsigned)X) atomicAdd(&hist[wz], 1);
            if ((unsigned)ww < (unsigned)X) atomicAdd(&hist[ww], 1);
        }
    }

    // Scalar tail for Y not a multiple of 4 (no-op for Y=4096)
    for (int y = (n4 << 2) + tid; y < Y; y += nt) {
        int w = duration[(size_t)b * Y + y] + (y < L ? 0 : MASK_PENALTY);
        w_out[(size_t)b * Y + y] = (float)w;
        if ((unsigned)w < (unsigned)X) atomicAdd(&hist[w], 1);
    }

    __syncthreads();

    // Histogram -> float output, vectorized
    float* __restrict__ hrow = h_out + (size_t)b * X;
    if ((X & 3) == 0) {
        float4* __restrict__ hrow4 = reinterpret_cast<float4*>(hrow);
        for (int i = tid; i < (X >> 2); i += nt) {
            float4 v;
            v.x = (float)hist[(i << 2) + 0];
            v.y = (float)hist[(i << 2) + 1];
            v.z = (float)hist[(i << 2) + 2];
            v.w = (float)hist[(i << 2) + 3];
            hrow4[i] = v;
        }
    } else {
        for (int i = tid; i < X; i += nt) hrow[i] = (float)hist[i];
    }
}

extern "C" void kernel_launch(void* const* d_in, const int* in_sizes, int n_in,
                              void* d_out, int out_size)
{
    const int* duration      = (const int*)d_in[0];
    const int* output_length = (const int*)d_in[1];

    const int B = in_sizes[1];          // 256
    const int Y = in_sizes[0] / B;      // 4096
    const int X = out_size / B - Y;     // 1024

    float* w_out = (float*)d_out;                   // weights_argmax: B*Y
    float* h_out = (float*)d_out + (size_t)B * Y;   // durations:      B*X

    const int threads = 512;
    const size_t smem = (size_t)X * sizeof(int);
    duration_calc_kernel<<<B, threads, smem>>>(duration, output_length,
                                               w_out, h_out, Y, X);
}